// round 1
// baseline (speedup 1.0000x reference)
#include <cuda_runtime.h>

#define B   8
#define N   2048
#define E   256
#define M   1024
#define CD  32
#define O   512
#define K2  512          // 2*E
#define NP  8192         // B*M
#define NPK 16384        // B*M*2
#define OUT_COOR_OFF 4194304   // B*O*M

// ---------------- scratch (static __device__ globals; no allocation) ------------
__device__ float g_D2[(size_t)B * N * N];       // 134 MB pairwise squared distances
__device__ float g_feaT[(size_t)B * N * E];     // 16 MB  fea transposed [b][n][e]
__device__ int   g_fps[B * M];
__device__ int   g_knn[B * M * 2];
__device__ float g_X[(size_t)NPK * K2];         // 32 MB  GEMM B-matrix [pk][c]
__device__ float g_Y[(size_t)O * NPK];          // 32 MB  GEMM output  [o][pk]
__device__ float g_scale[O];
__device__ float g_shift[O];

// ---------------- f32x2 helpers -------------------------------------------------
__device__ __forceinline__ unsigned long long pk2(float x) {
    unsigned u = __float_as_uint(x);
    unsigned long long r;
    asm("mov.b64 %0, {%1, %1};" : "=l"(r) : "r"(u));
    return r;
}
__device__ __forceinline__ void fma2(unsigned long long& d, unsigned long long a,
                                     unsigned long long b) {
    asm("fma.rn.f32x2 %0, %1, %2, %3;" : "=l"(d) : "l"(a), "l"(b), "l"(d));
}
__device__ __forceinline__ void unpk2(unsigned long long v, float& lo, float& hi) {
    unsigned a, b;
    asm("mov.b64 {%0, %1}, %2;" : "=r"(a), "=r"(b) : "l"(v));
    lo = __uint_as_float(a); hi = __uint_as_float(b);
}

// ---------------- 1. pairwise D2 (subtract-square form; exact-zero diagonal) ----
__global__ __launch_bounds__(256) void k_d2(const float* __restrict__ coor) {
    int bb = blockIdx.z;
    int it = blockIdx.y * 64, jt = blockIdx.x * 64;
    __shared__ float sA[64][33], sB[64][33];
    const float* cb = coor + (size_t)bb * N * CD;
    int t = threadIdx.x;
#pragma unroll
    for (int q = 0; q < 2; q++) {
        int f = q * 256 + t;              // float4 index, 512 total per tile
        int row = f >> 3;
        int c4  = (f & 7) * 4;
        float4 va = *(const float4*)(cb + (size_t)(it + row) * CD + c4);
        sA[row][c4] = va.x; sA[row][c4 + 1] = va.y; sA[row][c4 + 2] = va.z; sA[row][c4 + 3] = va.w;
        float4 vb = *(const float4*)(cb + (size_t)(jt + row) * CD + c4);
        sB[row][c4] = vb.x; sB[row][c4 + 1] = vb.y; sB[row][c4 + 2] = vb.z; sB[row][c4 + 3] = vb.w;
    }
    __syncthreads();
    int tj = (t & 15) * 4, ti = (t >> 4) * 4;
    float acc[4][4];
#pragma unroll
    for (int u = 0; u < 4; u++)
#pragma unroll
        for (int v = 0; v < 4; v++) acc[u][v] = 0.f;
#pragma unroll
    for (int c = 0; c < CD; c++) {
        float a0 = sA[ti + 0][c], a1 = sA[ti + 1][c], a2 = sA[ti + 2][c], a3 = sA[ti + 3][c];
        float b0 = sB[tj + 0][c], b1 = sB[tj + 1][c], b2 = sB[tj + 2][c], b3 = sB[tj + 3][c];
        float av[4] = {a0, a1, a2, a3}, bv[4] = {b0, b1, b2, b3};
#pragma unroll
        for (int u = 0; u < 4; u++)
#pragma unroll
            for (int v = 0; v < 4; v++) {
                float d = av[u] - bv[v];
                acc[u][v] = fmaf(d, d, acc[u][v]);
            }
    }
    float* Drow = g_D2 + (size_t)bb * N * N;
#pragma unroll
    for (int u = 0; u < 4; u++) {
        float4 w4 = make_float4(acc[u][0], acc[u][1], acc[u][2], acc[u][3]);
        *(float4*)(Drow + (size_t)(it + ti + u) * N + jt + tj) = w4;
    }
}

// ---------------- 2. farthest point sampling (one block per batch) --------------
__global__ __launch_bounds__(1024) void k_fps() {
    int bb = blockIdx.x;
    int t  = threadIdx.x;
    const float* Db = g_D2 + (size_t)bb * N * N;
    __shared__ unsigned long long swarp[32];
    __shared__ int sidx;
    float d0 = 1e10f, d1 = 1e10f;
    int i0 = 2 * t, i1 = 2 * t + 1;
    if (t == 0) g_fps[bb * M] = 0;
    int last = 0;
    for (int s = 1; s < M; s++) {
        float2 dd = *(const float2*)(Db + (size_t)last * N + 2 * t);
        d0 = fminf(d0, dd.x);
        d1 = fminf(d1, dd.y);
        float v; int vi;
        if (d0 >= d1) { v = d0; vi = i0; } else { v = d1; vi = i1; }
        unsigned key  = __float_as_uint(v);                 // all dists >= 0
        unsigned wmax = __reduce_max_sync(0xffffffffu, key);
        unsigned cand = (key == wmax) ? (unsigned)vi : 0xffffffffu;
        unsigned widx = __reduce_min_sync(0xffffffffu, cand);  // lowest idx on tie
        if ((t & 31) == 0)
            swarp[t >> 5] = ((unsigned long long)wmax << 32) | (unsigned long long)widx;
        __syncthreads();
        if (t < 32) {
            unsigned long long kv = swarp[t];
            unsigned hv   = (unsigned)(kv >> 32);
            unsigned hmax = __reduce_max_sync(0xffffffffu, hv);
            unsigned c2   = (hv == hmax) ? (unsigned)kv : 0xffffffffu;
            unsigned gidx = __reduce_min_sync(0xffffffffu, c2);
            if (t == 0) { sidx = (int)gidx; g_fps[bb * M + s] = (int)gidx; }
        }
        __syncthreads();
        last = sidx;
    }
}

// ---------------- 3. top-2 smallest per selected row (one warp per row) ---------
__global__ __launch_bounds__(256) void k_knn() {
    int gw   = (blockIdx.x * blockDim.x + threadIdx.x) >> 5;   // 0..8191
    int lane = threadIdx.x & 31;
    int bb = gw >> 10, j = gw & 1023;
    int r  = g_fps[bb * M + j];
    const float* row = g_D2 + (size_t)bb * N * N + (size_t)r * N;
    unsigned long long p1 = ~0ull, p2 = ~0ull;
    for (int col = lane; col < N; col += 32) {
        unsigned long long key =
            ((unsigned long long)__float_as_uint(row[col]) << 32) | (unsigned)col;
        if (key < p1)      { p2 = p1; p1 = key; }
        else if (key < p2) { p2 = key; }
    }
#pragma unroll
    for (int off = 16; off; off >>= 1) {
        unsigned long long q1 = __shfl_down_sync(0xffffffffu, p1, off);
        unsigned long long q2 = __shfl_down_sync(0xffffffffu, p2, off);
        unsigned long long n1 = p1 < q1 ? p1 : q1;
        unsigned long long m1 = p1 < q1 ? q1 : p1;
        unsigned long long n2 = p2 < q2 ? p2 : q2;
        p1 = n1;
        p2 = m1 < n2 ? m1 : n2;
    }
    if (lane == 0) {
        g_knn[2 * (bb * M + j)]     = (int)(p1 & 0xffffffffu);
        g_knn[2 * (bb * M + j) + 1] = (int)(p2 & 0xffffffffu);
    }
}

// ---------------- 4. transpose fea [b][e][n] -> [b][n][e] ------------------------
__global__ void k_transpose(const float* __restrict__ fea) {
    __shared__ float tile[32][33];
    int bx = blockIdx.x * 32, by = blockIdx.y * 32, bb = blockIdx.z;
    const float* src = fea + (size_t)bb * E * N;
#pragma unroll
    for (int k = 0; k < 32; k += 8)
        tile[threadIdx.y + k][threadIdx.x] =
            src[(size_t)(by + threadIdx.y + k) * N + bx + threadIdx.x];
    __syncthreads();
    float* dst = g_feaT + (size_t)bb * N * E;
#pragma unroll
    for (int k = 0; k < 32; k += 8)
        dst[(size_t)(bx + threadIdx.y + k) * E + by + threadIdx.x] =
            tile[threadIdx.x][threadIdx.y + k];
}

// ---------------- 5. build X [pk][c]: rows = [assist | center] -------------------
__global__ __launch_bounds__(256) void k_buildX() {
    int p  = blockIdx.x;                   // b*1024+j
    int bb = p >> 10;
    int c  = threadIdx.x;                  // 0..255
    int r  = g_fps[p];
    int n1 = g_knn[2 * p];
    int n2 = g_knn[2 * p + 1];
    const float* fT = g_feaT + (size_t)bb * N * E;
    float fc = fT[(size_t)r  * E + c];
    float f1 = fT[(size_t)n1 * E + c];
    float f2 = fT[(size_t)n2 * E + c];
    float* x0 = g_X + (size_t)(2 * p) * K2;
    x0[c]          = f1 - fc;
    x0[E + c]      = fc;
    x0[K2 + c]     = f2 - fc;
    x0[K2 + E + c] = fc;
}

// ---------------- 6. fp32 GEMM  Y[o][pk] = sum_c W[o][c] * X[pk][c] --------------
__global__ __launch_bounds__(256) void k_gemm(const float* __restrict__ Wm) {
    __shared__ __align__(16) float As[16][132];
    __shared__ __align__(16) float Bs[16][132];
    int pb = blockIdx.x * 128;   // N dim (pk)
    int ob = blockIdx.y * 128;   // M dim (o)
    int t  = threadIdx.x;
    int tx = t & 15, ty = t >> 4;
    unsigned long long acc[8][4];
#pragma unroll
    for (int u = 0; u < 8; u++)
#pragma unroll
        for (int v = 0; v < 4; v++) acc[u][v] = 0ull;

    for (int kb = 0; kb < K2; kb += 16) {
#pragma unroll
        for (int q = 0; q < 2; q++) {
            int f  = q * 256 + t;
            int o  = f >> 2;
            int kq = (f & 3) * 4;
            float4 va = *(const float4*)(Wm + (size_t)(ob + o) * K2 + kb + kq);
            As[kq][o] = va.x; As[kq + 1][o] = va.y; As[kq + 2][o] = va.z; As[kq + 3][o] = va.w;
            float4 vb = *(const float4*)(g_X + (size_t)(pb + o) * K2 + kb + kq);
            Bs[kq][o] = vb.x; Bs[kq + 1][o] = vb.y; Bs[kq + 2][o] = vb.z; Bs[kq + 3][o] = vb.w;
        }
        __syncthreads();
#pragma unroll
        for (int k = 0; k < 16; k++) {
            unsigned long long a2[8], b2[4];
#pragma unroll
            for (int u = 0; u < 8; u++) a2[u] = pk2(As[k][ty * 8 + u]);
#pragma unroll
            for (int v = 0; v < 4; v++)
                b2[v] = *(const unsigned long long*)&Bs[k][tx * 8 + v * 2];
#pragma unroll
            for (int u = 0; u < 8; u++)
#pragma unroll
                for (int v = 0; v < 4; v++) fma2(acc[u][v], a2[u], b2[v]);
        }
        __syncthreads();
    }
#pragma unroll
    for (int u = 0; u < 8; u++)
#pragma unroll
        for (int v = 0; v < 4; v++) {
            float lo, hi;
            unpk2(acc[u][v], lo, hi);
            *(float2*)&g_Y[(size_t)(ob + ty * 8 + u) * NPK + pb + tx * 8 + v * 2] =
                make_float2(lo, hi);
        }
}

// ---------------- 7. BN stats per channel (deterministic reduction) --------------
__global__ __launch_bounds__(256) void k_stats(const float* __restrict__ gamma,
                                               const float* __restrict__ beta) {
    int o = blockIdx.x;
    const float* yr = g_Y + (size_t)o * NPK;
    float s = 0.f, s2 = 0.f;
    for (int i = threadIdx.x; i < NPK; i += 256) {
        float v = yr[i];
        s += v;
        s2 = fmaf(v, v, s2);
    }
    __shared__ float sh[256], sh2[256];
    sh[threadIdx.x] = s; sh2[threadIdx.x] = s2;
    __syncthreads();
    for (int d = 128; d; d >>= 1) {
        if (threadIdx.x < d) {
            sh[threadIdx.x]  += sh[threadIdx.x + d];
            sh2[threadIdx.x] += sh2[threadIdx.x + d];
        }
        __syncthreads();
    }
    if (threadIdx.x == 0) {
        float mu   = sh[0] / (float)NPK;
        float var  = sh2[0] / (float)NPK - mu * mu;
        float rstd = rsqrtf(var + 1e-5f);
        float sc   = gamma[o] * rstd;
        g_scale[o] = sc;
        g_shift[o] = beta[o] - mu * sc;
    }
}

// ---------------- 8. BN apply + relu + max over k -> out_fea [b][o][m] -----------
__global__ __launch_bounds__(256) void k_final(float* __restrict__ out) {
    int lin = blockIdx.x * 256 + threadIdx.x;   // 512 * 8192
    int o = lin >> 13;
    int p = lin & 8191;
    float2 y = *(const float2*)&g_Y[(size_t)o * NPK + 2 * p];
    float sc = g_scale[o], sh = g_shift[o];
    float a = y.x * sc + sh;
    float b = y.y * sc + sh;
    float v = fmaxf(fmaxf(a, b), 0.f);
    int bb = p >> 10, j = p & 1023;
    out[(size_t)bb * O * M + (size_t)o * M + j] = v;
}

// ---------------- 9. coor_sampled [b][m][c] --------------------------------------
__global__ __launch_bounds__(256) void k_coor(const float* __restrict__ coor,
                                              float* __restrict__ out2) {
    int lin = blockIdx.x * 256 + threadIdx.x;   // B*M*CD = 262144
    int cc = lin & 31;
    int j  = (lin >> 5) & 1023;
    int bb = lin >> 15;
    int r  = g_fps[bb * M + j];
    out2[lin] = coor[(size_t)bb * N * CD + (size_t)r * CD + cc];
}

// ---------------- launch ---------------------------------------------------------
extern "C" void kernel_launch(void* const* d_in, const int* in_sizes, int n_in,
                              void* d_out, int out_size) {
    const float* fea   = (const float*)d_in[0];   // [8][256][2048]
    const float* coor  = (const float*)d_in[1];   // [8][2048][32]
    const float* Wm    = (const float*)d_in[2];   // [512][512]
    const float* gamma = (const float*)d_in[4];   // [512]
    const float* beta  = (const float*)d_in[5];   // [512]
    float* out  = (float*)d_out;
    float* out2 = out + OUT_COOR_OFF;

    k_transpose<<<dim3(N / 32, E / 32, B), dim3(32, 8)>>>(fea);
    k_d2<<<dim3(N / 64, N / 64, B), 256>>>(coor);
    k_fps<<<B, 1024>>>();
    k_knn<<<(B * M * 32) / 256, 256>>>();
    k_coor<<<(B * M * CD) / 256, 256>>>(coor, out2);
    k_buildX<<<NP, 256>>>();
    k_gemm<<<dim3(NPK / 128, O / 128), 256>>>(Wm);
    k_stats<<<O, 256>>>(gamma, beta);
    k_final<<<(O * NP) / 256, 256>>>(out);
}

// round 2
// speedup vs baseline: 1.0996x; 1.0996x over previous
#include <cuda_runtime.h>

typedef unsigned long long ull;

#define B   8
#define N   2048
#define E   256
#define M   1024
#define CD  32
#define O   512
#define NP  8192          // B*M
#define NPK 16384         // B*M*2
#define OUT_COOR_OFF 4194304   // B*O*M

// ---------------- scratch (static __device__ globals) ---------------------------
__device__ float g_D2[(size_t)B * N * N];        // 134 MB pairwise sq dists
__device__ float g_feaT[(size_t)B * N * E];      // 16 MB  fea transposed [b][n][e]
__device__ float g_ZT[(size_t)B * N * 1024];     // 64 MB  [bn][ Z1(512) | Z2(512) ]
__device__ float g_Y[(size_t)NPK * O];           // 32 MB  y [pk][o]
__device__ int   g_fps[B * M];
__device__ int   g_knn[B * M * 2];
__device__ float g_scale[O];
__device__ float g_shift[O];

// ---------------- f32x2 helpers -------------------------------------------------
__device__ __forceinline__ ull pk2(float x) {
    unsigned u = __float_as_uint(x);
    ull r;
    asm("mov.b64 %0, {%1, %1};" : "=l"(r) : "r"(u));
    return r;
}
__device__ __forceinline__ void fma2(ull& d, ull a, ull b) {
    asm("fma.rn.f32x2 %0, %1, %2, %3;" : "=l"(d) : "l"(a), "l"(b), "l"(d));
}
// d = a - b  (exact: fma(b, -1, a))
__device__ __forceinline__ ull sub2(ull a, ull b, ull negone) {
    ull d;
    asm("fma.rn.f32x2 %0, %1, %2, %3;" : "=l"(d) : "l"(b), "l"(negone), "l"(a));
    return d;
}
__device__ __forceinline__ void unpk2(ull v, float& lo, float& hi) {
    unsigned a, b;
    asm("mov.b64 {%0, %1}, %2;" : "=r"(a), "=r"(b) : "l"(v));
    lo = __uint_as_float(a); hi = __uint_as_float(b);
}

// ---------------- 1. transpose fea [b][e][n] -> [b][n][e] ------------------------
__global__ void k_transpose(const float* __restrict__ fea) {
    __shared__ float tile[32][33];
    int bx = blockIdx.x * 32, by = blockIdx.y * 32, bb = blockIdx.z;
    const float* src = fea + (size_t)bb * E * N;
#pragma unroll
    for (int k = 0; k < 32; k += 8)
        tile[threadIdx.y + k][threadIdx.x] =
            src[(size_t)(by + threadIdx.y + k) * N + bx + threadIdx.x];
    __syncthreads();
    float* dst = g_feaT + (size_t)bb * N * E;
#pragma unroll
    for (int k = 0; k < 32; k += 8)
        dst[(size_t)(bx + threadIdx.y + k) * E + by + threadIdx.x] =
            tile[threadIdx.x][threadIdx.y + k];
}

// ---------------- 2. pairwise D2, packed f32x2, 128x128 tiles --------------------
__global__ __launch_bounds__(256) void k_d2(const float* __restrict__ coor) {
    int bb = blockIdx.z;
    int it = blockIdx.y * 128, jt = blockIdx.x * 128;
    __shared__ __align__(16) float sA[32][132];
    __shared__ __align__(16) float sB[32][132];
    const float* cb = coor + (size_t)bb * N * CD;
    int t = threadIdx.x;
#pragma unroll
    for (int q = 0; q < 4; q++) {
        int f = q * 256 + t;              // float4 index, 1024 per tile side
        int row = f >> 3;
        int c4  = (f & 7) * 4;
        float4 va = *(const float4*)(cb + (size_t)(it + row) * CD + c4);
        sA[c4][row] = va.x; sA[c4 + 1][row] = va.y; sA[c4 + 2][row] = va.z; sA[c4 + 3][row] = va.w;
        float4 vb = *(const float4*)(cb + (size_t)(jt + row) * CD + c4);
        sB[c4][row] = vb.x; sB[c4 + 1][row] = vb.y; sB[c4 + 2][row] = vb.z; sB[c4 + 3][row] = vb.w;
    }
    __syncthreads();
    int tx = t & 15, ty = t >> 4;
    ull acc[8][4];
#pragma unroll
    for (int u = 0; u < 8; u++)
#pragma unroll
        for (int v = 0; v < 4; v++) acc[u][v] = 0ull;
    ull neg1 = pk2(-1.0f);
#pragma unroll
    for (int c = 0; c < CD; c++) {
        float4 fa = *(const float4*)&sA[c][ty * 8];
        float4 fb = *(const float4*)&sA[c][ty * 8 + 4];
        ull a2[8] = {pk2(fa.x), pk2(fa.y), pk2(fa.z), pk2(fa.w),
                     pk2(fb.x), pk2(fb.y), pk2(fb.z), pk2(fb.w)};
        const ull* pb = (const ull*)&sB[c][tx * 8];
        ull b2[4] = {pb[0], pb[1], pb[2], pb[3]};
#pragma unroll
        for (int u = 0; u < 8; u++)
#pragma unroll
            for (int v = 0; v < 4; v++) {
                ull d = sub2(a2[u], b2[v], neg1);
                fma2(acc[u][v], d, d);
            }
    }
    float* Drow = g_D2 + (size_t)bb * N * N;
#pragma unroll
    for (int u = 0; u < 8; u++) {
        float x0, x1, x2, x3, x4, x5, x6, x7;
        unpk2(acc[u][0], x0, x1); unpk2(acc[u][1], x2, x3);
        unpk2(acc[u][2], x4, x5); unpk2(acc[u][3], x6, x7);
        float* wp = Drow + (size_t)(it + ty * 8 + u) * N + jt + tx * 8;
        *(float4*)wp       = make_float4(x0, x1, x2, x3);
        *(float4*)(wp + 4) = make_float4(x4, x5, x6, x7);
    }
}

// ---------------- 3. FUSED: fps (blocks 0..7) + Z-GEMM (blocks 8..1031) ----------
__global__ __launch_bounds__(256) void k_fused(const float* __restrict__ Wm) {
    __shared__ __align__(16) float smemF[2 * 16 * 132];   // gemm tiles (16.9 KB)
    __shared__ ull sred[2][8];                            // fps stage-2 (dbl-buf)
    int t = threadIdx.x;

    if (blockIdx.x < 8) {
        // ============================ FPS ========================================
        int bb   = blockIdx.x;
        int lane = t & 31, wid = t >> 5;
        const float* Db = g_D2 + (size_t)bb * N * N;
        float d0 = 1e10f, d1 = 1e10f, d2 = 1e10f, d3 = 1e10f;
        float d4 = 1e10f, d5 = 1e10f, d6 = 1e10f, d7 = 1e10f;
        int base = t * 8;
        int last = 0;
        if (t == 0) g_fps[bb * M] = 0;
        for (int s = 1; s < M; s++) {
            const float4* rp = (const float4*)(Db + (size_t)last * N);
            float4 ra = rp[2 * t], rb = rp[2 * t + 1];
            d0 = fminf(d0, ra.x); d1 = fminf(d1, ra.y);
            d2 = fminf(d2, ra.z); d3 = fminf(d3, ra.w);
            d4 = fminf(d4, rb.x); d5 = fminf(d5, rb.y);
            d6 = fminf(d6, rb.z); d7 = fminf(d7, rb.w);
            // local argmax, lowest index wins ties (strict >)
            float vA = (d1 > d0) ? d1 : d0;  int jA = (d1 > d0) ? base + 1 : base;
            float vB = (d3 > d2) ? d3 : d2;  int jB = (d3 > d2) ? base + 3 : base + 2;
            float vC = (d5 > d4) ? d5 : d4;  int jC = (d5 > d4) ? base + 5 : base + 4;
            float vD = (d7 > d6) ? d7 : d6;  int jD = (d7 > d6) ? base + 7 : base + 6;
            float vAB = (vB > vA) ? vB : vA; int jAB = (vB > vA) ? jB : jA;
            float vCD = (vD > vC) ? vD : vC; int jCD = (vD > vC) ? jD : jC;
            float v   = (vCD > vAB) ? vCD : vAB;
            int   j   = (vCD > vAB) ? jCD : jAB;
            unsigned key  = __float_as_uint(v);               // dists >= 0
            unsigned wmax = __reduce_max_sync(0xffffffffu, key);
            unsigned ball = __ballot_sync(0xffffffffu, key == wmax);
            int src  = __ffs(ball) - 1;                       // lowest lane = lowest col
            int widx = __shfl_sync(0xffffffffu, j, src);
            if (lane == 0)
                sred[s & 1][wid] = ((ull)wmax << 32) | (unsigned)widx;
            __syncthreads();
            // redundant stage-2 in every warp (no 2nd barrier, no broadcast)
            ull kv = sred[s & 1][lane & 7];
            unsigned hv   = (unsigned)(kv >> 32);
            unsigned hmax = __reduce_max_sync(0xffffffffu, hv);
            unsigned bl2  = __ballot_sync(0xffffffffu, hv == hmax);
            int src2 = __ffs(bl2) - 1;                        // lowest warp = lowest col range
            last = __shfl_sync(0xffffffffu, (int)(unsigned)(kv & 0xffffffffu), src2);
            if (t == 0) g_fps[bb * M + s] = last;
        }
    } else {
        // ================ Z-GEMM: ZT[bn][o<512]=G1.f, ZT[bn][512+o]=(W2-W1).f ====
        int gb = blockIdx.x - 8;
        int ot = gb & 7, nt = gb >> 3;
        int ob = ot * 128, nb = nt * 128;
        float (*sF)[132] = (float(*)[132])smemF;
        float (*sG)[132] = (float(*)[132])(smemF + 16 * 132);
        int tx = t & 15, ty = t >> 4;
        ull acc[8][4];
#pragma unroll
        for (int u = 0; u < 8; u++)
#pragma unroll
            for (int v = 0; v < 4; v++) acc[u][v] = 0ull;

        for (int c0 = 0; c0 < 256; c0 += 16) {
#pragma unroll
            for (int q = 0; q < 2; q++) {
                int f  = q * 256 + t;
                int r  = f >> 2;
                int c4 = (f & 3) * 4;
                float4 va = *(const float4*)(g_feaT + (size_t)(nb + r) * E + c0 + c4);
                sF[c4][r] = va.x; sF[c4 + 1][r] = va.y; sF[c4 + 2][r] = va.z; sF[c4 + 3][r] = va.w;
                float4 wv;
                if (ob < 512) {
                    wv = *(const float4*)(Wm + (size_t)(ob + r) * 512 + c0 + c4);
                } else {
                    const float* wr = Wm + (size_t)(ob + r - 512) * 512;
                    float4 w1 = *(const float4*)(wr + c0 + c4);
                    float4 w2 = *(const float4*)(wr + 256 + c0 + c4);
                    wv = make_float4(w2.x - w1.x, w2.y - w1.y, w2.z - w1.z, w2.w - w1.w);
                }
                sG[c4][r] = wv.x; sG[c4 + 1][r] = wv.y; sG[c4 + 2][r] = wv.z; sG[c4 + 3][r] = wv.w;
            }
            __syncthreads();
#pragma unroll
            for (int k = 0; k < 16; k++) {
                float4 fa = *(const float4*)&sF[k][ty * 8];
                float4 fb = *(const float4*)&sF[k][ty * 8 + 4];
                ull a2[8] = {pk2(fa.x), pk2(fa.y), pk2(fa.z), pk2(fa.w),
                             pk2(fb.x), pk2(fb.y), pk2(fb.z), pk2(fb.w)};
                const ull* pb = (const ull*)&sG[k][tx * 8];
                ull b0 = pb[0], b1 = pb[1], b2v = pb[2], b3 = pb[3];
#pragma unroll
                for (int u = 0; u < 8; u++) {
                    fma2(acc[u][0], a2[u], b0);
                    fma2(acc[u][1], a2[u], b1);
                    fma2(acc[u][2], a2[u], b2v);
                    fma2(acc[u][3], a2[u], b3);
                }
            }
            __syncthreads();
        }
#pragma unroll
        for (int u = 0; u < 8; u++) {
            float x0, x1, x2, x3, x4, x5, x6, x7;
            unpk2(acc[u][0], x0, x1); unpk2(acc[u][1], x2, x3);
            unpk2(acc[u][2], x4, x5); unpk2(acc[u][3], x6, x7);
            float* zr = g_ZT + (size_t)(nb + ty * 8 + u) * 1024 + ob + tx * 8;
            *(float4*)zr       = make_float4(x0, x1, x2, x3);
            *(float4*)(zr + 4) = make_float4(x4, x5, x6, x7);
        }
    }
}

// ---------------- 4. top-2 smallest per selected row (one warp per row) ---------
__global__ __launch_bounds__(256) void k_knn() {
    int gw   = (blockIdx.x * blockDim.x + threadIdx.x) >> 5;
    int lane = threadIdx.x & 31;
    int bb = gw >> 10, j = gw & 1023;
    int r  = g_fps[bb * M + j];
    const float* row = g_D2 + (size_t)bb * N * N + (size_t)r * N;
    ull p1 = ~0ull, p2 = ~0ull;
    for (int col = lane; col < N; col += 32) {
        ull key = ((ull)__float_as_uint(row[col]) << 32) | (unsigned)col;
        if (key < p1)      { p2 = p1; p1 = key; }
        else if (key < p2) { p2 = key; }
    }
#pragma unroll
    for (int off = 16; off; off >>= 1) {
        ull q1 = __shfl_down_sync(0xffffffffu, p1, off);
        ull q2 = __shfl_down_sync(0xffffffffu, p2, off);
        ull n1 = p1 < q1 ? p1 : q1;
        ull m1 = p1 < q1 ? q1 : p1;
        ull n2 = p2 < q2 ? p2 : q2;
        p1 = n1;
        p2 = m1 < n2 ? m1 : n2;
    }
    if (lane == 0) {
        g_knn[2 * (bb * M + j)]     = (int)(p1 & 0xffffffffu);
        g_knn[2 * (bb * M + j) + 1] = (int)(p2 & 0xffffffffu);
    }
}

// ---------------- 5. assemble y[pk][o] = Z1[nk] + Z2[c] --------------------------
__global__ __launch_bounds__(256) void k_asm() {
    int t = threadIdx.x;
    int sub = t >> 7;                 // 0 -> neighbor1 row, 1 -> neighbor2 row
    int o4  = (t & 127) * 4;
    int pbase = blockIdx.x * 16;
#pragma unroll 4
    for (int pp = 0; pp < 16; pp++) {
        int p  = pbase + pp;
        int bb = p >> 10;
        int c  = g_fps[p];
        int nk = g_knn[2 * p + sub];
        const float* z1 = g_ZT + (size_t)(bb * N + nk) * 1024;
        const float* z2 = g_ZT + (size_t)(bb * N + c) * 1024 + 512;
        float4 a = *(const float4*)(z1 + o4);
        float4 b = *(const float4*)(z2 + o4);
        float4 y = make_float4(a.x + b.x, a.y + b.y, a.z + b.z, a.w + b.w);
        *(float4*)(g_Y + (size_t)(2 * p + sub) * O + o4) = y;
    }
}

// ---------------- 6. BN stats (deterministic) ------------------------------------
__global__ __launch_bounds__(256) void k_stats(const float* __restrict__ gamma,
                                               const float* __restrict__ beta) {
    int t   = threadIdx.x;
    int ocb = blockIdx.x * 32;
    int o   = ocb + (t & 31);
    int h   = t >> 5;
    float s = 0.f, s2 = 0.f;
    for (int r = h; r < NPK; r += 8) {
        float v = g_Y[(size_t)r * O + o];
        s += v;
        s2 = fmaf(v, v, s2);
    }
    __shared__ float ps[8][32], ps2[8][32];
    ps[h][t & 31] = s; ps2[h][t & 31] = s2;
    __syncthreads();
    if (t < 32) {
        float ss = 0.f, ss2 = 0.f;
#pragma unroll
        for (int i = 0; i < 8; i++) { ss += ps[i][t]; ss2 += ps2[i][t]; }
        float mu   = ss / (float)NPK;
        float var  = ss2 / (float)NPK - mu * mu;
        float rstd = rsqrtf(var + 1e-5f);
        float sc   = gamma[ocb + t] * rstd;
        g_scale[ocb + t] = sc;
        g_shift[ocb + t] = beta[ocb + t] - mu * sc;
    }
}

// ---------------- 7. BN apply + relu + max_k + transpose -> out[b][o][m] ---------
__global__ __launch_bounds__(256) void k_final(float* __restrict__ out) {
    __shared__ float sm[128][33];
    int t   = threadIdx.x;
    int jt  = blockIdx.x * 64;
    int ocb = blockIdx.y * 32;
    int bb  = blockIdx.z;
    size_t pk0 = ((size_t)bb * M + jt) * 2;
#pragma unroll
    for (int q = 0; q < 4; q++) {
        int f = q * 256 + t;
        int row = f >> 3;
        int oq  = (f & 7) * 4;
        float4 v = *(const float4*)(g_Y + (pk0 + row) * O + ocb + oq);
        sm[row][oq] = v.x; sm[row][oq + 1] = v.y; sm[row][oq + 2] = v.z; sm[row][oq + 3] = v.w;
    }
    __syncthreads();
    int oo = t >> 3;
    int jb = (t & 7) * 8;
    float sc = g_scale[ocb + oo], sh = g_shift[ocb + oo];
    float res[8];
#pragma unroll
    for (int jj = 0; jj < 8; jj++) {
        int r = 2 * (jb + jj);
        float a = fmaf(sm[r][oo],     sc, sh);
        float b = fmaf(sm[r + 1][oo], sc, sh);
        res[jj] = fmaxf(fmaxf(a, b), 0.f);
    }
    float* op = out + ((size_t)bb * O + ocb + oo) * M + jt + jb;
    *(float4*)op       = make_float4(res[0], res[1], res[2], res[3]);
    *(float4*)(op + 4) = make_float4(res[4], res[5], res[6], res[7]);
}

// ---------------- 8. coor_sampled [b][m][c] --------------------------------------
__global__ __launch_bounds__(256) void k_coor(const float* __restrict__ coor,
                                              float* __restrict__ out2) {
    int lin = blockIdx.x * 256 + threadIdx.x;   // B*M*CD = 262144
    int cc = lin & 31;
    int j  = (lin >> 5) & 1023;
    int bb = lin >> 15;
    int r  = g_fps[bb * M + j];
    out2[lin] = coor[(size_t)bb * N * CD + (size_t)r * CD + cc];
}

// ---------------- launch ---------------------------------------------------------
extern "C" void kernel_launch(void* const* d_in, const int* in_sizes, int n_in,
                              void* d_out, int out_size) {
    const float* fea   = (const float*)d_in[0];   // [8][256][2048]
    const float* coor  = (const float*)d_in[1];   // [8][2048][32]
    const float* Wm    = (const float*)d_in[2];   // [512][512]
    const float* gamma = (const float*)d_in[4];   // [512]
    const float* beta  = (const float*)d_in[5];   // [512]
    float* out  = (float*)d_out;
    float* out2 = out + OUT_COOR_OFF;

    k_transpose<<<dim3(N / 32, E / 32, B), dim3(32, 8)>>>(fea);
    k_d2<<<dim3(N / 128, N / 128, B), 256>>>(coor);
    k_fused<<<8 + 1024, 256>>>(Wm);               // fps on blocks 0..7, GEMM hidden under it
    k_knn<<<(B * M * 32) / 256, 256>>>();
    k_coor<<<(B * M * CD) / 256, 256>>>(coor, out2);
    k_asm<<<NP / 16, 256>>>();
    k_stats<<<O / 32, 256>>>(gamma, beta);
    k_final<<<dim3(M / 64, O / 32, B), 256>>>(out);
}

// round 3
// speedup vs baseline: 1.4031x; 1.2760x over previous
#include <cuda_runtime.h>

typedef unsigned long long ull;

#define B   8
#define N   2048
#define E   256
#define M   1024
#define CD  32
#define O   512
#define NP  8192          // B*M
#define NPK 16384         // B*M*2
#define OUT_COOR_OFF 4194304   // B*O*M

// ---------------- scratch (static __device__ globals) ---------------------------
__device__ float g_D2[(size_t)B * N * N];        // 134 MB pairwise sq dists (keep in L2!)
__device__ float g_feaT[(size_t)B * N * E];      // 16 MB  fea transposed [b][n][e]
__device__ float g_ZT[(size_t)B * N * 1024];     // 64 MB  [bn][ Z1(512) | Z2(512) ]
__device__ float g_Y[(size_t)NPK * O];           // 32 MB  y [pk][o]
__device__ int   g_fps[B * M];
__device__ int   g_knn[B * M * 2];
__device__ float g_scale[O];
__device__ float g_shift[O];

// ---------------- f32x2 helpers -------------------------------------------------
__device__ __forceinline__ ull pk2(float x) {
    unsigned u = __float_as_uint(x);
    ull r;
    asm("mov.b64 %0, {%1, %1};" : "=l"(r) : "r"(u));
    return r;
}
__device__ __forceinline__ void fma2(ull& d, ull a, ull b) {
    asm("fma.rn.f32x2 %0, %1, %2, %3;" : "=l"(d) : "l"(a), "l"(b), "l"(d));
}
// d = a - b  (exact: fma(b, -1, a))
__device__ __forceinline__ ull sub2(ull a, ull b, ull negone) {
    ull d;
    asm("fma.rn.f32x2 %0, %1, %2, %3;" : "=l"(d) : "l"(b), "l"(negone), "l"(a));
    return d;
}
__device__ __forceinline__ void unpk2(ull v, float& lo, float& hi) {
    unsigned a, b;
    asm("mov.b64 {%0, %1}, %2;" : "=r"(a), "=r"(b) : "l"(v));
    lo = __uint_as_float(a); hi = __uint_as_float(b);
}
__device__ __forceinline__ void pfL2(const void* p) {
    asm volatile("prefetch.global.L2 [%0];" :: "l"(p));
}

// ---------------- 1. transpose fea [b][e][n] -> [b][n][e] ------------------------
__global__ void k_transpose(const float* __restrict__ fea) {
    __shared__ float tile[32][33];
    int bx = blockIdx.x * 32, by = blockIdx.y * 32, bb = blockIdx.z;
    const float* src = fea + (size_t)bb * E * N;
#pragma unroll
    for (int k = 0; k < 32; k += 8)
        tile[threadIdx.y + k][threadIdx.x] =
            src[(size_t)(by + threadIdx.y + k) * N + bx + threadIdx.x];
    __syncthreads();
    float* dst = g_feaT + (size_t)bb * N * E;
#pragma unroll
    for (int k = 0; k < 32; k += 8)   // evict-first: don't displace D2 later
        __stcs(&dst[(size_t)(bx + threadIdx.y + k) * E + by + threadIdx.x],
               tile[threadIdx.x][threadIdx.y + k]);
}

// ---------------- 2. pairwise D2, packed f32x2, 128x128 tiles --------------------
__global__ __launch_bounds__(256) void k_d2(const float* __restrict__ coor) {
    int bb = blockIdx.z;
    int it = blockIdx.y * 128, jt = blockIdx.x * 128;
    __shared__ __align__(16) float sA[32][132];
    __shared__ __align__(16) float sB[32][132];
    const float* cb = coor + (size_t)bb * N * CD;
    int t = threadIdx.x;
#pragma unroll
    for (int q = 0; q < 4; q++) {
        int f = q * 256 + t;
        int row = f >> 3;
        int c4  = (f & 7) * 4;
        float4 va = *(const float4*)(cb + (size_t)(it + row) * CD + c4);
        sA[c4][row] = va.x; sA[c4 + 1][row] = va.y; sA[c4 + 2][row] = va.z; sA[c4 + 3][row] = va.w;
        float4 vb = *(const float4*)(cb + (size_t)(jt + row) * CD + c4);
        sB[c4][row] = vb.x; sB[c4 + 1][row] = vb.y; sB[c4 + 2][row] = vb.z; sB[c4 + 3][row] = vb.w;
    }
    __syncthreads();
    int tx = t & 15, ty = t >> 4;
    ull acc[8][4];
#pragma unroll
    for (int u = 0; u < 8; u++)
#pragma unroll
        for (int v = 0; v < 4; v++) acc[u][v] = 0ull;
    ull neg1 = pk2(-1.0f);
#pragma unroll
    for (int c = 0; c < CD; c++) {
        float4 fa = *(const float4*)&sA[c][ty * 8];
        float4 fb = *(const float4*)&sA[c][ty * 8 + 4];
        ull a2[8] = {pk2(fa.x), pk2(fa.y), pk2(fa.z), pk2(fa.w),
                     pk2(fb.x), pk2(fb.y), pk2(fb.z), pk2(fb.w)};
        const ull* pb = (const ull*)&sB[c][tx * 8];
        ull b2[4] = {pb[0], pb[1], pb[2], pb[3]};
#pragma unroll
        for (int u = 0; u < 8; u++)
#pragma unroll
            for (int v = 0; v < 4; v++) {
                ull d = sub2(a2[u], b2[v], neg1);
                fma2(acc[u][v], d, d);
            }
    }
    float* Drow = g_D2 + (size_t)bb * N * N;
#pragma unroll
    for (int u = 0; u < 8; u++) {
        float x0, x1, x2, x3, x4, x5, x6, x7;
        unpk2(acc[u][0], x0, x1); unpk2(acc[u][1], x2, x3);
        unpk2(acc[u][2], x4, x5); unpk2(acc[u][3], x6, x7);
        float* wp = Drow + (size_t)(it + ty * 8 + u) * N + jt + tx * 8;
        *(float4*)wp       = make_float4(x0, x1, x2, x3);   // default: allocate in L2
        *(float4*)(wp + 4) = make_float4(x4, x5, x6, x7);
    }
}

// ---------------- 3. FUSED: fps (blocks 0..7) + Z-GEMM (blocks 8..1031) ----------
__global__ __launch_bounds__(256) void k_fused(const float* __restrict__ Wm) {
    __shared__ __align__(16) float smemF[2 * 16 * 132];
    __shared__ ull sred[2][8];
    int t = threadIdx.x;

    if (blockIdx.x < 8) {
        // ============================ FPS ========================================
        int bb   = blockIdx.x;
        int lane = t & 31, wid = t >> 5;
        const float* Db = g_D2 + (size_t)bb * N * N;
        float d0 = 1e10f, d1 = 1e10f, d2 = 1e10f, d3 = 1e10f;
        float d4 = 1e10f, d5 = 1e10f, d6 = 1e10f, d7 = 1e10f;
        int base = t * 8;
        int last = 0;
        if (t == 0) g_fps[bb * M] = 0;
        pfL2(Db + lane * 64);                 // warm row 0
        for (int s = 1; s < M; s++) {
            const float4* rp = (const float4*)(Db + (size_t)last * N);
            float4 ra = rp[2 * t], rb = rp[2 * t + 1];
            d0 = fminf(d0, ra.x); d1 = fminf(d1, ra.y);
            d2 = fminf(d2, ra.z); d3 = fminf(d3, ra.w);
            d4 = fminf(d4, rb.x); d5 = fminf(d5, rb.y);
            d6 = fminf(d6, rb.z); d7 = fminf(d7, rb.w);
            float vA = (d1 > d0) ? d1 : d0;  int jA = (d1 > d0) ? base + 1 : base;
            float vB = (d3 > d2) ? d3 : d2;  int jB = (d3 > d2) ? base + 3 : base + 2;
            float vC = (d5 > d4) ? d5 : d4;  int jC = (d5 > d4) ? base + 5 : base + 4;
            float vD = (d7 > d6) ? d7 : d6;  int jD = (d7 > d6) ? base + 7 : base + 6;
            float vAB = (vB > vA) ? vB : vA; int jAB = (vB > vA) ? jB : jA;
            float vCD = (vD > vC) ? vD : vC; int jCD = (vD > vC) ? jD : jC;
            float v   = (vCD > vAB) ? vCD : vAB;
            int   j   = (vCD > vAB) ? jCD : jAB;
            unsigned key  = __float_as_uint(v);
            unsigned wmax = __reduce_max_sync(0xffffffffu, key);
            unsigned ball = __ballot_sync(0xffffffffu, key == wmax);
            int src  = __ffs(ball) - 1;
            int widx = __shfl_sync(0xffffffffu, j, src);
            // speculative prefetch: each warp pulls its own candidate row into L2
            {
                const float* prow = Db + (size_t)widx * N + lane * 64;
                pfL2(prow);
                pfL2(prow + 32);
            }
            if (lane == 0)
                sred[s & 1][wid] = ((ull)wmax << 32) | (unsigned)widx;
            __syncthreads();
            ull kv = sred[s & 1][lane & 7];
            unsigned hv   = (unsigned)(kv >> 32);
            unsigned hmax = __reduce_max_sync(0xffffffffu, hv);
            unsigned bl2  = __ballot_sync(0xffffffffu, hv == hmax);
            int src2 = __ffs(bl2) - 1;
            last = __shfl_sync(0xffffffffu, (int)(unsigned)(kv & 0xffffffffu), src2);
            if (t == 0) g_fps[bb * M + s] = last;
        }
    } else {
        // ================ Z-GEMM (all traffic evict-first; protect D2 in L2) =====
        int gb = blockIdx.x - 8;
        int ot = gb & 7, nt = gb >> 3;
        int ob = ot * 128, nb = nt * 128;
        float (*sF)[132] = (float(*)[132])smemF;
        float (*sG)[132] = (float(*)[132])(smemF + 16 * 132);
        int tx = t & 15, ty = t >> 4;
        ull acc[8][4];
#pragma unroll
        for (int u = 0; u < 8; u++)
#pragma unroll
            for (int v = 0; v < 4; v++) acc[u][v] = 0ull;

        for (int c0 = 0; c0 < 256; c0 += 16) {
#pragma unroll
            for (int q = 0; q < 2; q++) {
                int f  = q * 256 + t;
                int r  = f >> 2;
                int c4 = (f & 3) * 4;
                float4 va = __ldcs((const float4*)(g_feaT + (size_t)(nb + r) * E + c0 + c4));
                sF[c4][r] = va.x; sF[c4 + 1][r] = va.y; sF[c4 + 2][r] = va.z; sF[c4 + 3][r] = va.w;
                float4 wv;
                if (ob < 512) {
                    wv = *(const float4*)(Wm + (size_t)(ob + r) * 512 + c0 + c4);
                } else {
                    const float* wr = Wm + (size_t)(ob + r - 512) * 512;
                    float4 w1 = *(const float4*)(wr + c0 + c4);
                    float4 w2 = *(const float4*)(wr + 256 + c0 + c4);
                    wv = make_float4(w2.x - w1.x, w2.y - w1.y, w2.z - w1.z, w2.w - w1.w);
                }
                sG[c4][r] = wv.x; sG[c4 + 1][r] = wv.y; sG[c4 + 2][r] = wv.z; sG[c4 + 3][r] = wv.w;
            }
            __syncthreads();
#pragma unroll
            for (int k = 0; k < 16; k++) {
                float4 fa = *(const float4*)&sF[k][ty * 8];
                float4 fb = *(const float4*)&sF[k][ty * 8 + 4];
                ull a2[8] = {pk2(fa.x), pk2(fa.y), pk2(fa.z), pk2(fa.w),
                             pk2(fb.x), pk2(fb.y), pk2(fb.z), pk2(fb.w)};
                const ull* pb = (const ull*)&sG[k][tx * 8];
                ull b0 = pb[0], b1 = pb[1], b2v = pb[2], b3 = pb[3];
#pragma unroll
                for (int u = 0; u < 8; u++) {
                    fma2(acc[u][0], a2[u], b0);
                    fma2(acc[u][1], a2[u], b1);
                    fma2(acc[u][2], a2[u], b2v);
                    fma2(acc[u][3], a2[u], b3);
                }
            }
            __syncthreads();
        }
#pragma unroll
        for (int u = 0; u < 8; u++) {
            float x0, x1, x2, x3, x4, x5, x6, x7;
            unpk2(acc[u][0], x0, x1); unpk2(acc[u][1], x2, x3);
            unpk2(acc[u][2], x4, x5); unpk2(acc[u][3], x6, x7);
            float* zr = g_ZT + (size_t)(nb + ty * 8 + u) * 1024 + ob + tx * 8;
            __stcs((float4*)zr,       make_float4(x0, x1, x2, x3));   // evict-first
            __stcs((float4*)(zr + 4), make_float4(x4, x5, x6, x7));
        }
    }
}

// ---------------- 4. top-2 smallest per selected row (one warp per row) ---------
__global__ __launch_bounds__(256) void k_knn() {
    int gw   = (blockIdx.x * blockDim.x + threadIdx.x) >> 5;
    int lane = threadIdx.x & 31;
    int bb = gw >> 10, j = gw & 1023;
    int r  = g_fps[bb * M + j];
    const float* row = g_D2 + (size_t)bb * N * N + (size_t)r * N;
    ull p1 = ~0ull, p2 = ~0ull;
    for (int col = lane; col < N; col += 32) {
        ull key = ((ull)__float_as_uint(row[col]) << 32) | (unsigned)col;
        if (key < p1)      { p2 = p1; p1 = key; }
        else if (key < p2) { p2 = key; }
    }
#pragma unroll
    for (int off = 16; off; off >>= 1) {
        ull q1 = __shfl_down_sync(0xffffffffu, p1, off);
        ull q2 = __shfl_down_sync(0xffffffffu, p2, off);
        ull n1 = p1 < q1 ? p1 : q1;
        ull m1 = p1 < q1 ? q1 : p1;
        ull n2 = p2 < q2 ? p2 : q2;
        p1 = n1;
        p2 = m1 < n2 ? m1 : n2;
    }
    if (lane == 0) {
        g_knn[2 * (bb * M + j)]     = (int)(p1 & 0xffffffffu);
        g_knn[2 * (bb * M + j) + 1] = (int)(p2 & 0xffffffffu);
    }
}

// ---------------- 5. assemble y[pk][o] = Z1[nk] + Z2[c] --------------------------
__global__ __launch_bounds__(256) void k_asm() {
    int t = threadIdx.x;
    int sub = t >> 7;
    int o4  = (t & 127) * 4;
    int pbase = blockIdx.x * 16;
#pragma unroll 4
    for (int pp = 0; pp < 16; pp++) {
        int p  = pbase + pp;
        int bb = p >> 10;
        int c  = g_fps[p];
        int nk = g_knn[2 * p + sub];
        const float* z1 = g_ZT + (size_t)(bb * N + nk) * 1024;
        const float* z2 = g_ZT + (size_t)(bb * N + c) * 1024 + 512;
        float4 a = __ldcs((const float4*)(z1 + o4));
        float4 b = __ldcs((const float4*)(z2 + o4));
        float4 y = make_float4(a.x + b.x, a.y + b.y, a.z + b.z, a.w + b.w);
        *(float4*)(g_Y + (size_t)(2 * p + sub) * O + o4) = y;
    }
}

// ---------------- 6. BN stats (deterministic) ------------------------------------
__global__ __launch_bounds__(256) void k_stats(const float* __restrict__ gamma,
                                               const float* __restrict__ beta) {
    int t   = threadIdx.x;
    int ocb = blockIdx.x * 32;
    int o   = ocb + (t & 31);
    int h   = t >> 5;
    float s = 0.f, s2 = 0.f;
    for (int r = h; r < NPK; r += 8) {
        float v = g_Y[(size_t)r * O + o];
        s += v;
        s2 = fmaf(v, v, s2);
    }
    __shared__ float ps[8][32], ps2[8][32];
    ps[h][t & 31] = s; ps2[h][t & 31] = s2;
    __syncthreads();
    if (t < 32) {
        float ss = 0.f, ss2 = 0.f;
#pragma unroll
        for (int i = 0; i < 8; i++) { ss += ps[i][t]; ss2 += ps2[i][t]; }
        float mu   = ss / (float)NPK;
        float var  = ss2 / (float)NPK - mu * mu;
        float rstd = rsqrtf(var + 1e-5f);
        float sc   = gamma[ocb + t] * rstd;
        g_scale[ocb + t] = sc;
        g_shift[ocb + t] = beta[ocb + t] - mu * sc;
    }
}

// ---------------- 7. BN apply + relu + max_k + transpose -> out[b][o][m] ---------
__global__ __launch_bounds__(256) void k_final(float* __restrict__ out) {
    __shared__ float sm[128][33];
    int t   = threadIdx.x;
    int jt  = blockIdx.x * 64;
    int ocb = blockIdx.y * 32;
    int bb  = blockIdx.z;
    size_t pk0 = ((size_t)bb * M + jt) * 2;
#pragma unroll
    for (int q = 0; q < 4; q++) {
        int f = q * 256 + t;
        int row = f >> 3;
        int oq  = (f & 7) * 4;
        float4 v = *(const float4*)(g_Y + (pk0 + row) * O + ocb + oq);
        sm[row][oq] = v.x; sm[row][oq + 1] = v.y; sm[row][oq + 2] = v.z; sm[row][oq + 3] = v.w;
    }
    __syncthreads();
    int oo = t >> 3;
    int jb = (t & 7) * 8;
    float sc = g_scale[ocb + oo], sh = g_shift[ocb + oo];
    float res[8];
#pragma unroll
    for (int jj = 0; jj < 8; jj++) {
        int r = 2 * (jb + jj);
        float a = fmaf(sm[r][oo],     sc, sh);
        float b = fmaf(sm[r + 1][oo], sc, sh);
        res[jj] = fmaxf(fmaxf(a, b), 0.f);
    }
    float* op = out + ((size_t)bb * O + ocb + oo) * M + jt + jb;
    *(float4*)op       = make_float4(res[0], res[1], res[2], res[3]);
    *(float4*)(op + 4) = make_float4(res[4], res[5], res[6], res[7]);
}

// ---------------- 8. coor_sampled [b][m][c] --------------------------------------
__global__ __launch_bounds__(256) void k_coor(const float* __restrict__ coor,
                                              float* __restrict__ out2) {
    int lin = blockIdx.x * 256 + threadIdx.x;
    int cc = lin & 31;
    int j  = (lin >> 5) & 1023;
    int bb = lin >> 15;
    int r  = g_fps[bb * M + j];
    out2[lin] = coor[(size_t)bb * N * CD + (size_t)r * CD + cc];
}

// ---------------- launch ---------------------------------------------------------
extern "C" void kernel_launch(void* const* d_in, const int* in_sizes, int n_in,
                              void* d_out, int out_size) {
    const float* fea   = (const float*)d_in[0];
    const float* coor  = (const float*)d_in[1];
    const float* Wm    = (const float*)d_in[2];
    const float* gamma = (const float*)d_in[4];
    const float* beta  = (const float*)d_in[5];
    float* out  = (float*)d_out;
    float* out2 = out + OUT_COOR_OFF;

    k_transpose<<<dim3(N / 32, E / 32, B), dim3(32, 8)>>>(fea);
    k_d2<<<dim3(N / 128, N / 128, B), 256>>>(coor);
    k_fused<<<8 + 1024, 256>>>(Wm);
    k_knn<<<(B * M * 32) / 256, 256>>>();
    k_coor<<<(B * M * CD) / 256, 256>>>(coor, out2);
    k_asm<<<NP / 16, 256>>>();
    k_stats<<<O / 32, 256>>>(gamma, beta);
    k_final<<<dim3(M / 64, O / 32, B), 256>>>(out);
}